// round 14
// baseline (speedup 1.0000x reference)
#include <cuda_runtime.h>
#include <cuda_bf16.h>
#include <cuda_fp16.h>
#include <math.h>
#include <stdint.h>

#define T_STEPS 512
#define BATCH   64
#define TB      (T_STEPS*BATCH)   // 32768
#define EMB     400
#define NHID    1150

// ================= PTX helpers (sm_80+ only — no 'a' features!) =================
__device__ __forceinline__ uint32_t smem_u32(const void* p) {
    uint32_t a;
    asm("{ .reg .u64 t; cvta.to.shared.u64 t, %1; cvt.u32.u64 %0, t; }" : "=r"(a) : "l"(p));
    return a;
}
__device__ __forceinline__ void ldsm_x4(uint32_t* r, uint32_t addr) {
    asm volatile("ldmatrix.sync.aligned.m8n8.x4.shared.b16 {%0,%1,%2,%3}, [%4];"
        : "=r"(r[0]), "=r"(r[1]), "=r"(r[2]), "=r"(r[3]) : "r"(addr));
}
__device__ __forceinline__ void ldsm_x2(uint32_t* r, uint32_t addr) {
    asm volatile("ldmatrix.sync.aligned.m8n8.x2.shared.b16 {%0,%1}, [%2];"
        : "=r"(r[0]), "=r"(r[1]) : "r"(addr));
}
__device__ __forceinline__ void mma_fp16(float* c, const uint32_t* a, const uint32_t* b) {
    asm volatile("mma.sync.aligned.m16n8k16.row.col.f32.f16.f16.f32 "
        "{%0,%1,%2,%3}, {%4,%5,%6,%7}, {%8,%9}, {%0,%1,%2,%3};"
        : "+f"(c[0]), "+f"(c[1]), "+f"(c[2]), "+f"(c[3])
        : "r"(a[0]), "r"(a[1]), "r"(a[2]), "r"(a[3]), "r"(b[0]), "r"(b[1]));
}
__device__ __forceinline__ void cp_async16(uint32_t s, const void* g) {
    asm volatile("cp.async.cg.shared.global [%0], [%1], 16;" :: "r"(s), "l"(g) : "memory");
}
#define CP_COMMIT() asm volatile("cp.async.commit_group;" ::: "memory")
#define CP_WAIT0()  asm volatile("cp.async.wait_group 0;" ::: "memory")
#define CP_WAIT1()  asm volatile("cp.async.wait_group 1;" ::: "memory")
#define CP_WAIT2()  asm volatile("cp.async.wait_group 2;" ::: "memory")
#define CP_WAIT3()  asm volatile("cp.async.wait_group 3;" ::: "memory")

// ================= scratch (device globals) =================
__device__ float g_xg[(size_t)TB*4*NHID];                       // 603 MB
__device__ int g_count;                                         // monotonic barrier counter
__device__ __align__(16) __half g_xf[(size_t)TB*1152];          // X fp16
__device__ __align__(16) __half g_wf[4608ull*1152];             // W fp16 (proj or scan)
__device__ __align__(16) __half g_hfp[2][64*1152];              // h fp16, double-buffered

// ================= embedding gather, fp16 =================
__global__ void embed_f16_kernel(const int* __restrict__ tok, const float* __restrict__ ew) {
    int i = blockIdx.x * blockDim.x + threadIdx.x;     // over TB * 112 (448/4)
    if (i >= TB * 112) return;
    int r = i / 112, c4 = i - r * 112;
    float4 v = make_float4(0.f, 0.f, 0.f, 0.f);
    if (c4 < 100) v = *(const float4*)(ew + (size_t)tok[r] * EMB + c4 * 4);
    __half2 p0 = __floats2half2_rn(v.x, v.y);
    __half2 p1 = __floats2half2_rn(v.z, v.w);
    uint2 u = make_uint2(*(uint32_t*)&p0, *(uint32_t*)&p1);
    *(uint2*)&g_xf[(size_t)r * 448 + c4 * 4] = u;
}

// ================= fp16 weight convert =================
__global__ void conv_w_f16_kernel(const float* __restrict__ W, int N, int K, int KP, int NP,
                                  __half* __restrict__ o) {
    size_t idx = (size_t)blockIdx.x * blockDim.x + threadIdx.x;
    if (idx >= (size_t)NP * KP) return;
    int k = (int)(idx % KP);
    size_t n = idx / KP;
    float v = (k < K && n < (size_t)N) ? W[n * K + k] : 0.f;
    o[idx] = __float2half_rn(v);
}

// ================= fp16 HMMA projection GEMM (R11 winner, unchanged) =========
#define PSTR 72
#define PT16 (128*PSTR)     // halves per tile

template<int KP>
__global__ void __launch_bounds__(256, 1) proj_f16_kernel(
    const __half* __restrict__ Xf, const __half* __restrict__ Wf,
    const float* __restrict__ bi, const float* __restrict__ bh,
    float* __restrict__ Y, int Nreal)
{
    extern __shared__ __align__(16) __half psm[];
    constexpr int KT = KP / 64;

    int tid = threadIdx.x;
    int wid = tid >> 5, lane = tid & 31;
    int warp_m = wid & 1, warp_n = wid >> 1;
    size_t mb = (size_t)blockIdx.y * 128;
    size_t nb = (size_t)blockIdx.x * 128;

    uint32_t sbase = smem_u32(psm);

    auto stage = [&](int t) {
        uint32_t b0 = sbase + (uint32_t)(t % 3) * (2 * PT16 * 2);
        int kc = t * 64;
#pragma unroll
        for (int i = 0; i < 4; i++) {
            int e = i * 256 + tid;
            int row = e >> 3, seg = e & 7;
            uint32_t so = (uint32_t)((row * PSTR + seg * 8) * 2);
            cp_async16(b0 + so,            Xf + (mb + row) * KP + kc + seg * 8);
            cp_async16(b0 + PT16 * 2 + so, Wf + (nb + row) * KP + kc + seg * 8);
        }
    };

    float acc[4][4][4];
#pragma unroll
    for (int i = 0; i < 4; i++)
#pragma unroll
        for (int j = 0; j < 4; j++)
#pragma unroll
            for (int q = 0; q < 4; q++) acc[i][j][q] = 0.f;

    stage(0); CP_COMMIT();
    if (KT > 1) { stage(1); CP_COMMIT(); }

    for (int t = 0; t < KT; t++) {
        if (t + 2 < KT) { stage(t + 2); CP_COMMIT(); CP_WAIT2(); }
        else if (t + 1 < KT) { CP_WAIT1(); }
        else { CP_WAIT0(); }
        __syncthreads();

        uint32_t b0 = sbase + (uint32_t)(t % 3) * (2 * PT16 * 2);
#pragma unroll
        for (int kf = 0; kf < 4; kf++) {
            uint32_t a[4][4], b[4][2];
#pragma unroll
            for (int fm = 0; fm < 4; fm++) {
                uint32_t ao = (uint32_t)(((warp_m * 64 + fm * 16 + (lane & 15)) * PSTR
                               + kf * 16 + (lane >> 4) * 8) * 2);
                ldsm_x4(a[fm], b0 + ao);
            }
#pragma unroll
            for (int fn = 0; fn < 4; fn++) {
                uint32_t bo = (uint32_t)(((warp_n * 32 + fn * 8 + (lane & 7)) * PSTR
                               + kf * 16 + ((lane >> 3) & 1) * 8) * 2);
                ldsm_x2(b[fn], b0 + PT16 * 2 + bo);
            }
#pragma unroll
            for (int fm = 0; fm < 4; fm++)
#pragma unroll
                for (int fn = 0; fn < 4; fn++)
                    mma_fp16(acc[fm][fn], a[fm], b[fn]);
        }
        __syncthreads();
    }

    int group = lane >> 2, tig = lane & 3;
#pragma unroll
    for (int fn = 0; fn < 4; fn++) {
        int n = (int)nb + warp_n * 32 + fn * 8 + 2 * tig;
        if (n < Nreal) {
            float bx = bi[n] + bh[n];
            float by = bi[n + 1] + bh[n + 1];
#pragma unroll
            for (int fm = 0; fm < 4; fm++) {
                size_t m = mb + warp_m * 64 + fm * 16 + group;
                float2 v0 = {acc[fm][fn][0] + bx, acc[fm][fn][1] + by};
                *(float2*)&Y[m * (size_t)Nreal + n] = v0;
                float2 v1 = {acc[fm][fn][2] + bx, acc[fm][fn][3] + by};
                *(float2*)&Y[(m + 8) * (size_t)Nreal + n] = v1;
            }
        }
    }
}

// ================= zero h buffers + barrier counter =================
__global__ void zero_hb_kernel() {
    int i = blockIdx.x * blockDim.x + threadIdx.x;
    if (i < 2 * 64 * 1152 / 2) ((uint32_t*)g_hfp)[i] = 0u;
    if (i == 0) g_count = 0;
}

// ================= fast activations (MUFU-based, err ~2^-20) =================
__device__ __forceinline__ float fsigmoid_(float x) {
    return __fdividef(1.f, 1.f + __expf(-x));
}
__device__ __forceinline__ float ftanh_(float x) {
    x = fminf(fmaxf(x, -15.f), 15.f);      // avoid inf/inf
    float e = __expf(2.f * x);
    return __fdividef(e - 1.f, e + 1.f);
}

// ================= fp16 HMMA persistent LSTM scan, warp-decoupled ============
// Block owns 8 units x 4 gates = 32 gate rows (n = q*8+ui). 4 warps,
// warp w = batch rows [w*16, w*16+16). Each warp's A-fragments touch ONLY its
// own 16 h-rows -> h staging is warp-private (per-warp ring slice, per-thread
// cp.async groups, consume after wait_group + __syncwarp). NO __syncthreads
// in the chunk loop. R14 FIX: dst stride per staging iter is 2 segs = 32 B
// (was 64 B -> overran ASTR row and the SMEM allocation).
template<int H, int KP, bool WX>
__global__ void __launch_bounds__(128, 1) scan_fp16_kernel(
    const float* __restrict__ xg,
    const __half* __restrict__ whh,
    float* __restrict__ out, int nb)
{
    constexpr int WSTR = KP + 8;
    constexpr int ASTR = 136;
    constexpr int NCH  = KP / 128;
    constexpr int G    = 4 * H;
    constexpr int SEGS = KP / 8;

    extern __shared__ __align__(16) char smx[];
    __half* Wh = (__half*)smx;
    __half* Ah = Wh + 32 * WSTR;          // per-warp: [4 bufs][16 rows][ASTR]

    int tid = threadIdx.x;
    int w = tid >> 5, lane = tid & 31;
    int g8 = lane >> 2, tig = lane & 3;
    int u0 = blockIdx.x * 8;
    bool uvalid = (u0 + 2 * tig) < H;

    for (int idx = tid; idx < 32 * SEGS; idx += 128) {
        int n = idx / SEGS, seg = idx - n * SEGS;
        int q = n >> 3, ui = n & 7, unit = u0 + ui;
        uint4 vh = {0,0,0,0};
        if (unit < H)
            vh = *(const uint4*)(whh + (size_t)(q * H + unit) * KP + seg * 8);
        *(uint4*)&Wh[n * WSTR + seg * 8] = vh;
    }
    __syncthreads();

    uint32_t wh_base = smem_u32(Wh);
    // per-warp ring base
    uint32_t ah_base = smem_u32(Ah) + (uint32_t)(w * 4 * 16 * ASTR * 2);

    // warp-private staging decomposition: 16 rows x 16 segs, 8 per lane
    int s_row = lane & 15;                 // row within warp's 16
    int s_seg0 = lane >> 4;                // 0/1; lane covers segs s_seg0 + 2*i

    float cst[4] = {0.f, 0.f, 0.f, 0.f};

    int* cntp = &g_count;
    int m_row = w * 16 + g8;

    float2 xv[8];
    auto load_xv = [&](int t) {
#pragma unroll
        for (int mi = 0; mi < 2; mi++)
#pragma unroll
            for (int q = 0; q < 4; q++) {
                xv[mi * 4 + q] = make_float2(0.f, 0.f);
                if (uvalid) {
                    int m = m_row + mi * 8;
                    xv[mi * 4 + q] = *(const float2*)(xg + ((size_t)t * 64 + m) * G
                                                      + q * H + u0 + 2 * tig);
                }
            }
    };
    load_xv(0);

    for (int t = 0; t < T_STEPS; t++) {
        if (t > 0) {
            if (tid == 0) {
                int target = nb * t, v;
                do {
                    asm volatile("ld.acquire.gpu.global.s32 %0, [%1];"
                                 : "=r"(v) : "l"(cntp));
                } while (v < target);
            }
            __syncthreads();
        }

        const __half* hh = g_hfp[t & 1] + (size_t)(w * 16) * 1152;

        // warp-private: stage this warp's 16 rows of chunk c into buf c&3
        auto stage_chunk = [&](int c) {
            int b = c & 3, cc = c * 128;
            const __half* src = hh + (size_t)s_row * 1152 + cc + s_seg0 * 8;
            uint32_t dst = ah_base + (uint32_t)(((b * 16 + s_row) * ASTR + s_seg0 * 8) * 2);
#pragma unroll
            for (int i = 0; i < 8; i++)
                cp_async16(dst + (uint32_t)(i * 32), src + i * 16);   // 2 segs = 32 B
        };

        float acc[4][4];
#pragma unroll
        for (int q = 0; q < 4; q++)
#pragma unroll
            for (int j = 0; j < 4; j++) acc[q][j] = 0.f;

        stage_chunk(0); CP_COMMIT();
        stage_chunk(1); CP_COMMIT();
        stage_chunk(2); CP_COMMIT();

        for (int c = 0; c < NCH; c++) {
            if (c + 3 < NCH) { stage_chunk(c + 3); CP_COMMIT(); CP_WAIT3(); }
            else {
                int r = NCH - 1 - c;
                if (r >= 3)      CP_WAIT3();
                else if (r == 2) CP_WAIT2();
                else if (r == 1) CP_WAIT1();
                else             CP_WAIT0();
            }
            __syncwarp();
            int b = c & 3;
#pragma unroll
            for (int j = 0; j < 8; j++) {
                uint32_t a[4];
                uint32_t a_off = ah_base + (uint32_t)(((b * 16 + (lane & 15)) * ASTR
                                  + j * 16 + (lane >> 4) * 8) * 2);
                ldsm_x4(a, a_off);
#pragma unroll
                for (int nf = 0; nf < 4; nf++) {
                    uint32_t bh[2];
                    uint32_t b_off = (uint32_t)(((nf * 8 + (lane & 7)) * WSTR
                                      + c * 128 + j * 16 + ((lane >> 3) & 1) * 8) * 2);
                    ldsm_x2(bh, wh_base + b_off);
                    mma_fp16(acc[nf], a, bh);
                }
            }
        }

        // ---- cell update: compute h, write ONLY hw, then arrive ----
        __half* hw = g_hfp[(t + 1) & 1];
        float hv[2][2];
#pragma unroll
        for (int mi = 0; mi < 2; mi++) {
#pragma unroll
            for (int uu = 0; uu < 2; uu++) {
                float xi = uu ? xv[mi * 4 + 0].y : xv[mi * 4 + 0].x;
                float xf = uu ? xv[mi * 4 + 1].y : xv[mi * 4 + 1].x;
                float xgg = uu ? xv[mi * 4 + 2].y : xv[mi * 4 + 2].x;
                float xo = uu ? xv[mi * 4 + 3].y : xv[mi * 4 + 3].x;
                float iraw = acc[0][mi * 2 + uu] + xi;
                float fraw = acc[1][mi * 2 + uu] + xf;
                float graw = acc[2][mi * 2 + uu] + xgg;
                float oraw = acc[3][mi * 2 + uu] + xo;
                float cn = fsigmoid_(fraw) * cst[mi * 2 + uu]
                         + fsigmoid_(iraw) * ftanh_(graw);
                cst[mi * 2 + uu] = cn;
                hv[mi][uu] = fsigmoid_(oraw) * ftanh_(cn);
            }
            if (uvalid) {
                int m = m_row + mi * 8;
                __half2 hp = __floats2half2_rn(hv[mi][0], hv[mi][1]);
                *(uint32_t*)&hw[(size_t)m * 1152 + u0 + 2 * tig] = *(uint32_t*)&hp;
            }
        }
        __threadfence();
        __syncthreads();
        if (tid == 0)
            asm volatile("red.release.gpu.global.add.s32 [%0], %1;"
                         :: "l"(cntp), "r"(1) : "memory");

        // ---- hidden in the wait window: out stores, X stores, next xv ----
#pragma unroll
        for (int mi = 0; mi < 2; mi++) {
            int m = m_row + mi * 8;
            if (uvalid)
                *(float2*)&out[((size_t)t * 64 + m) * H + u0 + 2 * tig]
                    = make_float2(hv[mi][0], hv[mi][1]);
            if (WX) {
                uint32_t packed = 0u;
                if (uvalid) {
                    __half2 hp = __floats2half2_rn(hv[mi][0], hv[mi][1]);
                    packed = *(uint32_t*)&hp;
                }
                *(uint32_t*)&g_xf[((size_t)t * 64 + m) * 1152 + u0 + 2 * tig] = packed;
            }
        }
        if (t + 1 < T_STEPS) load_xv(t + 1);
    }
}

// ================= launch =================
extern "C" void kernel_launch(void* const* d_in, const int* in_sizes, int n_in,
                              void* d_out, int out_size)
{
    (void)in_sizes; (void)n_in; (void)out_size;
    const int*   tok = (const int*)d_in[0];
    const float* ew  = (const float*)d_in[1];
    const float* wih[3] = {(const float*)d_in[2], (const float*)d_in[6],  (const float*)d_in[10]};
    const float* whh[3] = {(const float*)d_in[3], (const float*)d_in[7],  (const float*)d_in[11]};
    const float* bih[3] = {(const float*)d_in[4], (const float*)d_in[8],  (const float*)d_in[12]};
    const float* bhh[3] = {(const float*)d_in[5], (const float*)d_in[9],  (const float*)d_in[13]};

    float* out  = (float*)d_out;
    float* out0 = out;
    float* out1 = out0 + (size_t)TB * NHID;
    float* out2 = out1 + (size_t)TB * NHID;

    void* p;
    cudaGetSymbolAddress(&p, g_xg);  float* xgf = (float*)p;
    cudaGetSymbolAddress(&p, g_xf);  __half* xf = (__half*)p;
    cudaGetSymbolAddress(&p, g_wf);  __half* wf = (__half*)p;

    const int PSM = 3 * 2 * PT16 * 2;                                    // 110,592 B
    const int SSM_BIG = (32 * (1152 + 8) + 4 * 64 * 136) * 2;            // 143,872 B
    const int SSM_SM  = (32 * (512 + 8)  + 4 * 64 * 136) * 2;            // 102,912 B
    cudaFuncSetAttribute(proj_f16_kernel<448>,
                         cudaFuncAttributeMaxDynamicSharedMemorySize, PSM);
    cudaFuncSetAttribute(proj_f16_kernel<1152>,
                         cudaFuncAttributeMaxDynamicSharedMemorySize, PSM);
    cudaFuncSetAttribute(scan_fp16_kernel<1150, 1152, true>,
                         cudaFuncAttributeMaxDynamicSharedMemorySize, SSM_BIG);
    cudaFuncSetAttribute(scan_fp16_kernel<400, 512, false>,
                         cudaFuncAttributeMaxDynamicSharedMemorySize, SSM_SM);

    auto cdiv = [](size_t a, int b) { return (int)((a + b - 1) / b); };
    const int ZHB = ((2 * 64 * 1152 / 2) + 255) / 256;

    embed_f16_kernel<<<cdiv((size_t)TB * 112, 256), 256>>>(tok, ew);

    // ---- layer 0: 400 -> 1150 ----
    conv_w_f16_kernel<<<cdiv(4608ull * 448, 256), 256>>>(wih[0], 4 * NHID, EMB, 448, 4608, wf);
    proj_f16_kernel<448><<<dim3(36, 256), 256, PSM>>>(xf, wf, bih[0], bhh[0], xgf, 4 * NHID);
    conv_w_f16_kernel<<<cdiv(4608ull * 1152, 256), 256>>>(whh[0], 4 * NHID, NHID, 1152, 4608, wf);
    zero_hb_kernel<<<ZHB, 256>>>();
    scan_fp16_kernel<1150, 1152, true><<<144, 128, SSM_BIG>>>(xgf, wf, out0, 144);

    // ---- layer 1: 1150 -> 1150 ----  (X written by scan0)
    conv_w_f16_kernel<<<cdiv(4608ull * 1152, 256), 256>>>(wih[1], 4 * NHID, NHID, 1152, 4608, wf);
    proj_f16_kernel<1152><<<dim3(36, 256), 256, PSM>>>(xf, wf, bih[1], bhh[1], xgf, 4 * NHID);
    conv_w_f16_kernel<<<cdiv(4608ull * 1152, 256), 256>>>(whh[1], 4 * NHID, NHID, 1152, 4608, wf);
    zero_hb_kernel<<<ZHB, 256>>>();
    scan_fp16_kernel<1150, 1152, true><<<144, 128, SSM_BIG>>>(xgf, wf, out1, 144);

    // ---- layer 2: 1150 -> 400 ----  (X written by scan1)
    conv_w_f16_kernel<<<cdiv(1664ull * 1152, 256), 256>>>(wih[2], 4 * 400, NHID, 1152, 1664, wf);
    proj_f16_kernel<1152><<<dim3(13, 256), 256, PSM>>>(xf, wf, bih[2], bhh[2], xgf, 4 * 400);
    conv_w_f16_kernel<<<cdiv(1600ull * 512, 256), 256>>>(whh[2], 4 * 400, 400, 512, 1600, wf);
    zero_hb_kernel<<<ZHB, 256>>>();
    scan_fp16_kernel<400, 512, false><<<50, 128, SSM_SM>>>(xgf, wf, out2, 50);
}

// round 15
// speedup vs baseline: 1.3653x; 1.3653x over previous
#include <cuda_runtime.h>
#include <cuda_bf16.h>
#include <cuda_fp16.h>
#include <math.h>
#include <stdint.h>

#define T_STEPS 512
#define BATCH   64
#define TB      (T_STEPS*BATCH)   // 32768
#define EMB     400
#define NHID    1150

// ================= PTX helpers (sm_80+ only — no 'a' features!) =================
__device__ __forceinline__ uint32_t smem_u32(const void* p) {
    uint32_t a;
    asm("{ .reg .u64 t; cvta.to.shared.u64 t, %1; cvt.u32.u64 %0, t; }" : "=r"(a) : "l"(p));
    return a;
}
__device__ __forceinline__ void ldsm_x4(uint32_t* r, uint32_t addr) {
    asm volatile("ldmatrix.sync.aligned.m8n8.x4.shared.b16 {%0,%1,%2,%3}, [%4];"
        : "=r"(r[0]), "=r"(r[1]), "=r"(r[2]), "=r"(r[3]) : "r"(addr));
}
__device__ __forceinline__ void ldsm_x2(uint32_t* r, uint32_t addr) {
    asm volatile("ldmatrix.sync.aligned.m8n8.x2.shared.b16 {%0,%1}, [%2];"
        : "=r"(r[0]), "=r"(r[1]) : "r"(addr));
}
__device__ __forceinline__ void mma_fp16(float* c, const uint32_t* a, const uint32_t* b) {
    asm volatile("mma.sync.aligned.m16n8k16.row.col.f32.f16.f16.f32 "
        "{%0,%1,%2,%3}, {%4,%5,%6,%7}, {%8,%9}, {%0,%1,%2,%3};"
        : "+f"(c[0]), "+f"(c[1]), "+f"(c[2]), "+f"(c[3])
        : "r"(a[0]), "r"(a[1]), "r"(a[2]), "r"(a[3]), "r"(b[0]), "r"(b[1]));
}
__device__ __forceinline__ void cp_async16(uint32_t s, const void* g) {
    asm volatile("cp.async.cg.shared.global [%0], [%1], 16;" :: "r"(s), "l"(g) : "memory");
}
#define CP_COMMIT() asm volatile("cp.async.commit_group;" ::: "memory")
#define CP_WAIT0()  asm volatile("cp.async.wait_group 0;" ::: "memory")
#define CP_WAIT1()  asm volatile("cp.async.wait_group 1;" ::: "memory")
#define CP_WAIT2()  asm volatile("cp.async.wait_group 2;" ::: "memory")
#define CP_WAIT3()  asm volatile("cp.async.wait_group 3;" ::: "memory")

// ================= scratch (device globals) =================
__device__ float g_xg[(size_t)TB*4*NHID];                       // 603 MB
__device__ int g_count;                                         // monotonic barrier counter
__device__ __align__(16) __half g_xf[(size_t)TB*1152];          // X fp16
__device__ __align__(16) __half g_wf[4608ull*1152];             // W fp16 (proj or scan)
__device__ __align__(16) __half g_hfp[2][64*1152];              // h fp16, double-buffered

// ================= embedding gather, fp16 =================
__global__ void embed_f16_kernel(const int* __restrict__ tok, const float* __restrict__ ew) {
    int i = blockIdx.x * blockDim.x + threadIdx.x;     // over TB * 112 (448/4)
    if (i >= TB * 112) return;
    int r = i / 112, c4 = i - r * 112;
    float4 v = make_float4(0.f, 0.f, 0.f, 0.f);
    if (c4 < 100) v = *(const float4*)(ew + (size_t)tok[r] * EMB + c4 * 4);
    __half2 p0 = __floats2half2_rn(v.x, v.y);
    __half2 p1 = __floats2half2_rn(v.z, v.w);
    uint2 u = make_uint2(*(uint32_t*)&p0, *(uint32_t*)&p1);
    *(uint2*)&g_xf[(size_t)r * 448 + c4 * 4] = u;
}

// ================= fp16 weight convert =================
__global__ void conv_w_f16_kernel(const float* __restrict__ W, int N, int K, int KP, int NP,
                                  __half* __restrict__ o) {
    size_t idx = (size_t)blockIdx.x * blockDim.x + threadIdx.x;
    if (idx >= (size_t)NP * KP) return;
    int k = (int)(idx % KP);
    size_t n = idx / KP;
    float v = (k < K && n < (size_t)N) ? W[n * K + k] : 0.f;
    o[idx] = __float2half_rn(v);
}

// ================= fp16 HMMA projection GEMM (R11 winner, unchanged) =========
#define PSTR 72
#define PT16 (128*PSTR)     // halves per tile

template<int KP>
__global__ void __launch_bounds__(256, 1) proj_f16_kernel(
    const __half* __restrict__ Xf, const __half* __restrict__ Wf,
    const float* __restrict__ bi, const float* __restrict__ bh,
    float* __restrict__ Y, int Nreal)
{
    extern __shared__ __align__(16) __half psm[];
    constexpr int KT = KP / 64;

    int tid = threadIdx.x;
    int wid = tid >> 5, lane = tid & 31;
    int warp_m = wid & 1, warp_n = wid >> 1;
    size_t mb = (size_t)blockIdx.y * 128;
    size_t nb = (size_t)blockIdx.x * 128;

    uint32_t sbase = smem_u32(psm);

    auto stage = [&](int t) {
        uint32_t b0 = sbase + (uint32_t)(t % 3) * (2 * PT16 * 2);
        int kc = t * 64;
#pragma unroll
        for (int i = 0; i < 4; i++) {
            int e = i * 256 + tid;
            int row = e >> 3, seg = e & 7;
            uint32_t so = (uint32_t)((row * PSTR + seg * 8) * 2);
            cp_async16(b0 + so,            Xf + (mb + row) * KP + kc + seg * 8);
            cp_async16(b0 + PT16 * 2 + so, Wf + (nb + row) * KP + kc + seg * 8);
        }
    };

    float acc[4][4][4];
#pragma unroll
    for (int i = 0; i < 4; i++)
#pragma unroll
        for (int j = 0; j < 4; j++)
#pragma unroll
            for (int q = 0; q < 4; q++) acc[i][j][q] = 0.f;

    stage(0); CP_COMMIT();
    if (KT > 1) { stage(1); CP_COMMIT(); }

    for (int t = 0; t < KT; t++) {
        if (t + 2 < KT) { stage(t + 2); CP_COMMIT(); CP_WAIT2(); }
        else if (t + 1 < KT) { CP_WAIT1(); }
        else { CP_WAIT0(); }
        __syncthreads();

        uint32_t b0 = sbase + (uint32_t)(t % 3) * (2 * PT16 * 2);
#pragma unroll
        for (int kf = 0; kf < 4; kf++) {
            uint32_t a[4][4], b[4][2];
#pragma unroll
            for (int fm = 0; fm < 4; fm++) {
                uint32_t ao = (uint32_t)(((warp_m * 64 + fm * 16 + (lane & 15)) * PSTR
                               + kf * 16 + (lane >> 4) * 8) * 2);
                ldsm_x4(a[fm], b0 + ao);
            }
#pragma unroll
            for (int fn = 0; fn < 4; fn++) {
                uint32_t bo = (uint32_t)(((warp_n * 32 + fn * 8 + (lane & 7)) * PSTR
                               + kf * 16 + ((lane >> 3) & 1) * 8) * 2);
                ldsm_x2(b[fn], b0 + PT16 * 2 + bo);
            }
#pragma unroll
            for (int fm = 0; fm < 4; fm++)
#pragma unroll
                for (int fn = 0; fn < 4; fn++)
                    mma_fp16(acc[fm][fn], a[fm], b[fn]);
        }
        __syncthreads();
    }

    int group = lane >> 2, tig = lane & 3;
#pragma unroll
    for (int fn = 0; fn < 4; fn++) {
        int n = (int)nb + warp_n * 32 + fn * 8 + 2 * tig;
        if (n < Nreal) {
            float bx = bi[n] + bh[n];
            float by = bi[n + 1] + bh[n + 1];
#pragma unroll
            for (int fm = 0; fm < 4; fm++) {
                size_t m = mb + warp_m * 64 + fm * 16 + group;
                float2 v0 = {acc[fm][fn][0] + bx, acc[fm][fn][1] + by};
                *(float2*)&Y[m * (size_t)Nreal + n] = v0;
                float2 v1 = {acc[fm][fn][2] + bx, acc[fm][fn][3] + by};
                *(float2*)&Y[(m + 8) * (size_t)Nreal + n] = v1;
            }
        }
    }
}

// ================= zero h buffers + barrier counter =================
__global__ void zero_hb_kernel() {
    int i = blockIdx.x * blockDim.x + threadIdx.x;
    if (i < 2 * 64 * 1152 / 2) ((uint32_t*)g_hfp)[i] = 0u;
    if (i == 0) g_count = 0;
}

// ================= fast activations (MUFU-based, err ~2^-20) =================
__device__ __forceinline__ float fsigmoid_(float x) {
    return __fdividef(1.f, 1.f + __expf(-x));
}
__device__ __forceinline__ float ftanh_(float x) {
    x = fminf(fmaxf(x, -15.f), 15.f);      // avoid inf/inf
    float e = __expf(2.f * x);
    return __fdividef(e - 1.f, e + 1.f);
}

// ================= fp16 HMMA persistent LSTM scan, warp-decoupled v2 =========
// Block owns 8 units x 4 gates = 32 gate rows. 4 warps, warp w = batch rows
// [w*16, w*16+16). h staging is warp-private BUT with R12-grade coalescing:
// per cp.async instruction, lanes 0-15 cover one row's 256 B contiguously,
// lanes 16-31 the next row (R14's transposed mapping caused ~16 wavefronts/
// instr and the regression). No __syncthreads in the chunk loop.
template<int H, int KP, bool WX>
__global__ void __launch_bounds__(128, 1) scan_fp16_kernel(
    const float* __restrict__ xg,
    const __half* __restrict__ whh,
    float* __restrict__ out, int nb)
{
    constexpr int WSTR = KP + 8;
    constexpr int ASTR = 136;
    constexpr int NCH  = KP / 128;
    constexpr int G    = 4 * H;
    constexpr int SEGS = KP / 8;

    extern __shared__ __align__(16) char smx[];
    __half* Wh = (__half*)smx;
    __half* Ah = Wh + 32 * WSTR;          // per-warp: [4 bufs][16 rows][ASTR]

    int tid = threadIdx.x;
    int w = tid >> 5, lane = tid & 31;
    int g8 = lane >> 2, tig = lane & 3;
    int u0 = blockIdx.x * 8;
    bool uvalid = (u0 + 2 * tig) < H;

    for (int idx = tid; idx < 32 * SEGS; idx += 128) {
        int n = idx / SEGS, seg = idx - n * SEGS;
        int q = n >> 3, ui = n & 7, unit = u0 + ui;
        uint4 vh = {0,0,0,0};
        if (unit < H)
            vh = *(const uint4*)(whh + (size_t)(q * H + unit) * KP + seg * 8);
        *(uint4*)&Wh[n * WSTR + seg * 8] = vh;
    }
    __syncthreads();

    uint32_t wh_base = smem_u32(Wh);
    uint32_t ah_base = smem_u32(Ah) + (uint32_t)(w * 4 * 16 * ASTR * 2);

    // coalesced warp-private staging: per instr i, row = i*2 + (lane>>4),
    // seg = lane&15 -> lanes 0-15 cover a full 256 B row contiguously.
    int s_seg  = lane & 15;
    int s_half = lane >> 4;

    float cst[4] = {0.f, 0.f, 0.f, 0.f};

    int* cntp = &g_count;
    int m_row = w * 16 + g8;

    float2 xv[8];
    auto load_xv = [&](int t) {
#pragma unroll
        for (int mi = 0; mi < 2; mi++)
#pragma unroll
            for (int q = 0; q < 4; q++) {
                xv[mi * 4 + q] = make_float2(0.f, 0.f);
                if (uvalid) {
                    int m = m_row + mi * 8;
                    xv[mi * 4 + q] = *(const float2*)(xg + ((size_t)t * 64 + m) * G
                                                      + q * H + u0 + 2 * tig);
                }
            }
    };
    load_xv(0);

    for (int t = 0; t < T_STEPS; t++) {
        if (t > 0) {
            if (tid == 0) {
                int target = nb * t, v;
                do {
                    asm volatile("ld.acquire.gpu.global.s32 %0, [%1];"
                                 : "=r"(v) : "l"(cntp));
                } while (v < target);
            }
            __syncthreads();
        }

        const __half* hh = g_hfp[t & 1] + (size_t)(w * 16) * 1152;

        auto stage_chunk = [&](int c) {
            int b = c & 3, cc = c * 128;
#pragma unroll
            for (int i = 0; i < 8; i++) {
                int row = i * 2 + s_half;
                cp_async16(ah_base + (uint32_t)(((b * 16 + row) * ASTR + s_seg * 8) * 2),
                           hh + (size_t)row * 1152 + cc + s_seg * 8);
            }
        };

        float acc[4][4];
#pragma unroll
        for (int q = 0; q < 4; q++)
#pragma unroll
            for (int j = 0; j < 4; j++) acc[q][j] = 0.f;

        stage_chunk(0); CP_COMMIT();
        stage_chunk(1); CP_COMMIT();
        stage_chunk(2); CP_COMMIT();

        for (int c = 0; c < NCH; c++) {
            if (c + 3 < NCH) { stage_chunk(c + 3); CP_COMMIT(); CP_WAIT3(); }
            else {
                int r = NCH - 1 - c;
                if (r >= 3)      CP_WAIT3();
                else if (r == 2) CP_WAIT2();
                else if (r == 1) CP_WAIT1();
                else             CP_WAIT0();
            }
            __syncwarp();
            int b = c & 3;
#pragma unroll
            for (int j = 0; j < 8; j++) {
                uint32_t a[4];
                uint32_t a_off = ah_base + (uint32_t)(((b * 16 + (lane & 15)) * ASTR
                                  + j * 16 + (lane >> 4) * 8) * 2);
                ldsm_x4(a, a_off);
#pragma unroll
                for (int nf = 0; nf < 4; nf++) {
                    uint32_t bh[2];
                    uint32_t b_off = (uint32_t)(((nf * 8 + (lane & 7)) * WSTR
                                      + c * 128 + j * 16 + ((lane >> 3) & 1) * 8) * 2);
                    ldsm_x2(bh, wh_base + b_off);
                    mma_fp16(acc[nf], a, bh);
                }
            }
        }

        // ---- cell update: compute h, write ONLY hw, then arrive ----
        __half* hw = g_hfp[(t + 1) & 1];
        float hv[2][2];
#pragma unroll
        for (int mi = 0; mi < 2; mi++) {
#pragma unroll
            for (int uu = 0; uu < 2; uu++) {
                float xi = uu ? xv[mi * 4 + 0].y : xv[mi * 4 + 0].x;
                float xf = uu ? xv[mi * 4 + 1].y : xv[mi * 4 + 1].x;
                float xgg = uu ? xv[mi * 4 + 2].y : xv[mi * 4 + 2].x;
                float xo = uu ? xv[mi * 4 + 3].y : xv[mi * 4 + 3].x;
                float iraw = acc[0][mi * 2 + uu] + xi;
                float fraw = acc[1][mi * 2 + uu] + xf;
                float graw = acc[2][mi * 2 + uu] + xgg;
                float oraw = acc[3][mi * 2 + uu] + xo;
                float cn = fsigmoid_(fraw) * cst[mi * 2 + uu]
                         + fsigmoid_(iraw) * ftanh_(graw);
                cst[mi * 2 + uu] = cn;
                hv[mi][uu] = fsigmoid_(oraw) * ftanh_(cn);
            }
            if (uvalid) {
                int m = m_row + mi * 8;
                __half2 hp = __floats2half2_rn(hv[mi][0], hv[mi][1]);
                *(uint32_t*)&hw[(size_t)m * 1152 + u0 + 2 * tig] = *(uint32_t*)&hp;
            }
        }
        __threadfence();
        __syncthreads();
        if (tid == 0)
            asm volatile("red.release.gpu.global.add.s32 [%0], %1;"
                         :: "l"(cntp), "r"(1) : "memory");

        // ---- hidden in the wait window: out stores, X stores, next xv ----
#pragma unroll
        for (int mi = 0; mi < 2; mi++) {
            int m = m_row + mi * 8;
            if (uvalid)
                *(float2*)&out[((size_t)t * 64 + m) * H + u0 + 2 * tig]
                    = make_float2(hv[mi][0], hv[mi][1]);
            if (WX) {
                uint32_t packed = 0u;
                if (uvalid) {
                    __half2 hp = __floats2half2_rn(hv[mi][0], hv[mi][1]);
                    packed = *(uint32_t*)&hp;
                }
                *(uint32_t*)&g_xf[((size_t)t * 64 + m) * 1152 + u0 + 2 * tig] = packed;
            }
        }
        if (t + 1 < T_STEPS) load_xv(t + 1);
    }
}

// ================= launch =================
extern "C" void kernel_launch(void* const* d_in, const int* in_sizes, int n_in,
                              void* d_out, int out_size)
{
    (void)in_sizes; (void)n_in; (void)out_size;
    const int*   tok = (const int*)d_in[0];
    const float* ew  = (const float*)d_in[1];
    const float* wih[3] = {(const float*)d_in[2], (const float*)d_in[6],  (const float*)d_in[10]};
    const float* whh[3] = {(const float*)d_in[3], (const float*)d_in[7],  (const float*)d_in[11]};
    const float* bih[3] = {(const float*)d_in[4], (const float*)d_in[8],  (const float*)d_in[12]};
    const float* bhh[3] = {(const float*)d_in[5], (const float*)d_in[9],  (const float*)d_in[13]};

    float* out  = (float*)d_out;
    float* out0 = out;
    float* out1 = out0 + (size_t)TB * NHID;
    float* out2 = out1 + (size_t)TB * NHID;

    void* p;
    cudaGetSymbolAddress(&p, g_xg);  float* xgf = (float*)p;
    cudaGetSymbolAddress(&p, g_xf);  __half* xf = (__half*)p;
    cudaGetSymbolAddress(&p, g_wf);  __half* wf = (__half*)p;

    const int PSM = 3 * 2 * PT16 * 2;                                    // 110,592 B
    const int SSM_BIG = (32 * (1152 + 8) + 4 * 64 * 136) * 2;            // 143,872 B
    const int SSM_SM  = (32 * (512 + 8)  + 4 * 64 * 136) * 2;            // 102,912 B
    cudaFuncSetAttribute(proj_f16_kernel<448>,
                         cudaFuncAttributeMaxDynamicSharedMemorySize, PSM);
    cudaFuncSetAttribute(proj_f16_kernel<1152>,
                         cudaFuncAttributeMaxDynamicSharedMemorySize, PSM);
    cudaFuncSetAttribute(scan_fp16_kernel<1150, 1152, true>,
                         cudaFuncAttributeMaxDynamicSharedMemorySize, SSM_BIG);
    cudaFuncSetAttribute(scan_fp16_kernel<400, 512, false>,
                         cudaFuncAttributeMaxDynamicSharedMemorySize, SSM_SM);

    auto cdiv = [](size_t a, int b) { return (int)((a + b - 1) / b); };
    const int ZHB = ((2 * 64 * 1152 / 2) + 255) / 256;

    embed_f16_kernel<<<cdiv((size_t)TB * 112, 256), 256>>>(tok, ew);

    // ---- layer 0: 400 -> 1150 ----
    conv_w_f16_kernel<<<cdiv(4608ull * 448, 256), 256>>>(wih[0], 4 * NHID, EMB, 448, 4608, wf);
    proj_f16_kernel<448><<<dim3(36, 256), 256, PSM>>>(xf, wf, bih[0], bhh[0], xgf, 4 * NHID);
    conv_w_f16_kernel<<<cdiv(4608ull * 1152, 256), 256>>>(whh[0], 4 * NHID, NHID, 1152, 4608, wf);
    zero_hb_kernel<<<ZHB, 256>>>();
    scan_fp16_kernel<1150, 1152, true><<<144, 128, SSM_BIG>>>(xgf, wf, out0, 144);

    // ---- layer 1: 1150 -> 1150 ----  (X written by scan0)
    conv_w_f16_kernel<<<cdiv(4608ull * 1152, 256), 256>>>(wih[1], 4 * NHID, NHID, 1152, 4608, wf);
    proj_f16_kernel<1152><<<dim3(36, 256), 256, PSM>>>(xf, wf, bih[1], bhh[1], xgf, 4 * NHID);
    conv_w_f16_kernel<<<cdiv(4608ull * 1152, 256), 256>>>(whh[1], 4 * NHID, NHID, 1152, 4608, wf);
    zero_hb_kernel<<<ZHB, 256>>>();
    scan_fp16_kernel<1150, 1152, true><<<144, 128, SSM_BIG>>>(xgf, wf, out1, 144);

    // ---- layer 2: 1150 -> 400 ----  (X written by scan1)
    conv_w_f16_kernel<<<cdiv(1664ull * 1152, 256), 256>>>(wih[2], 4 * 400, NHID, 1152, 1664, wf);
    proj_f16_kernel<1152><<<dim3(13, 256), 256, PSM>>>(xf, wf, bih[2], bhh[2], xgf, 4 * 400);
    conv_w_f16_kernel<<<cdiv(1600ull * 512, 256), 256>>>(whh[2], 4 * 400, 400, 512, 1600, wf);
    zero_hb_kernel<<<ZHB, 256>>>();
    scan_fp16_kernel<400, 512, false><<<50, 128, SSM_SM>>>(xgf, wf, out2, 50);
}

// round 16
// speedup vs baseline: 1.5633x; 1.1450x over previous
#include <cuda_runtime.h>
#include <cuda_bf16.h>
#include <cuda_fp16.h>
#include <math.h>
#include <stdint.h>

#define T_STEPS 512
#define BATCH   64
#define TB      (T_STEPS*BATCH)   // 32768
#define EMB     400
#define NHID    1150

// ================= PTX helpers (sm_80+ only — no 'a' features!) =================
__device__ __forceinline__ uint32_t smem_u32(const void* p) {
    uint32_t a;
    asm("{ .reg .u64 t; cvta.to.shared.u64 t, %1; cvt.u32.u64 %0, t; }" : "=r"(a) : "l"(p));
    return a;
}
__device__ __forceinline__ void ldsm_x4(uint32_t* r, uint32_t addr) {
    asm volatile("ldmatrix.sync.aligned.m8n8.x4.shared.b16 {%0,%1,%2,%3}, [%4];"
        : "=r"(r[0]), "=r"(r[1]), "=r"(r[2]), "=r"(r[3]) : "r"(addr));
}
__device__ __forceinline__ void ldsm_x2(uint32_t* r, uint32_t addr) {
    asm volatile("ldmatrix.sync.aligned.m8n8.x2.shared.b16 {%0,%1}, [%2];"
        : "=r"(r[0]), "=r"(r[1]) : "r"(addr));
}
__device__ __forceinline__ void mma_fp16(float* c, const uint32_t* a, const uint32_t* b) {
    asm volatile("mma.sync.aligned.m16n8k16.row.col.f32.f16.f16.f32 "
        "{%0,%1,%2,%3}, {%4,%5,%6,%7}, {%8,%9}, {%0,%1,%2,%3};"
        : "+f"(c[0]), "+f"(c[1]), "+f"(c[2]), "+f"(c[3])
        : "r"(a[0]), "r"(a[1]), "r"(a[2]), "r"(a[3]), "r"(b[0]), "r"(b[1]));
}
__device__ __forceinline__ void cp_async16(uint32_t s, const void* g) {
    asm volatile("cp.async.cg.shared.global [%0], [%1], 16;" :: "r"(s), "l"(g) : "memory");
}
#define CP_COMMIT() asm volatile("cp.async.commit_group;" ::: "memory")
#define CP_WAIT0()  asm volatile("cp.async.wait_group 0;" ::: "memory")
#define CP_WAIT1()  asm volatile("cp.async.wait_group 1;" ::: "memory")
#define CP_WAIT2()  asm volatile("cp.async.wait_group 2;" ::: "memory")
#define CP_WAIT3()  asm volatile("cp.async.wait_group 3;" ::: "memory")

// ================= scratch (device globals) =================
__device__ float g_xg[(size_t)TB*4*NHID];                       // 603 MB
__device__ int g_count;                                         // monotonic barrier counter
__device__ __align__(16) __half g_xf[(size_t)TB*1152];          // X fp16
__device__ __align__(16) __half g_wf[4608ull*1152];             // W fp16 (proj or scan)
__device__ __align__(16) __half g_hfp[2][64*1152];              // h fp16, double-buffered

// ================= embedding gather, fp16 =================
__global__ void embed_f16_kernel(const int* __restrict__ tok, const float* __restrict__ ew) {
    int i = blockIdx.x * blockDim.x + threadIdx.x;     // over TB * 112 (448/4)
    if (i >= TB * 112) return;
    int r = i / 112, c4 = i - r * 112;
    float4 v = make_float4(0.f, 0.f, 0.f, 0.f);
    if (c4 < 100) v = *(const float4*)(ew + (size_t)tok[r] * EMB + c4 * 4);
    __half2 p0 = __floats2half2_rn(v.x, v.y);
    __half2 p1 = __floats2half2_rn(v.z, v.w);
    uint2 u = make_uint2(*(uint32_t*)&p0, *(uint32_t*)&p1);
    *(uint2*)&g_xf[(size_t)r * 448 + c4 * 4] = u;
}

// ================= fp16 weight convert =================
__global__ void conv_w_f16_kernel(const float* __restrict__ W, int N, int K, int KP, int NP,
                                  __half* __restrict__ o) {
    size_t idx = (size_t)blockIdx.x * blockDim.x + threadIdx.x;
    if (idx >= (size_t)NP * KP) return;
    int k = (int)(idx % KP);
    size_t n = idx / KP;
    float v = (k < K && n < (size_t)N) ? W[n * K + k] : 0.f;
    o[idx] = __float2half_rn(v);
}

// ================= fp16 HMMA projection GEMM (2-slot ring, 2 blocks/SM) ======
#define PSTR 72
#define PT16 (128*PSTR)     // halves per tile

template<int KP>
__global__ void __launch_bounds__(256, 2) proj_f16_kernel(
    const __half* __restrict__ Xf, const __half* __restrict__ Wf,
    const float* __restrict__ bi, const float* __restrict__ bh,
    float* __restrict__ Y, int Nreal)
{
    extern __shared__ __align__(16) __half psm[];
    constexpr int KT = KP / 64;

    int tid = threadIdx.x;
    int wid = tid >> 5, lane = tid & 31;
    int warp_m = wid & 1, warp_n = wid >> 1;
    size_t mb = (size_t)blockIdx.y * 128;
    size_t nb = (size_t)blockIdx.x * 128;

    uint32_t sbase = smem_u32(psm);

    auto stage = [&](int t) {
        uint32_t b0 = sbase + (uint32_t)(t & 1) * (2 * PT16 * 2);
        int kc = t * 64;
#pragma unroll
        for (int i = 0; i < 4; i++) {
            int e = i * 256 + tid;
            int row = e >> 3, seg = e & 7;
            uint32_t so = (uint32_t)((row * PSTR + seg * 8) * 2);
            cp_async16(b0 + so,            Xf + (mb + row) * KP + kc + seg * 8);
            cp_async16(b0 + PT16 * 2 + so, Wf + (nb + row) * KP + kc + seg * 8);
        }
    };

    float acc[4][4][4];
#pragma unroll
    for (int i = 0; i < 4; i++)
#pragma unroll
        for (int j = 0; j < 4; j++)
#pragma unroll
            for (int q = 0; q < 4; q++) acc[i][j][q] = 0.f;

    stage(0); CP_COMMIT();

    for (int t = 0; t < KT; t++) {
        if (t + 1 < KT) { stage(t + 1); CP_COMMIT(); CP_WAIT1(); }
        else            { CP_WAIT0(); }
        __syncthreads();

        uint32_t b0 = sbase + (uint32_t)(t & 1) * (2 * PT16 * 2);
#pragma unroll
        for (int kf = 0; kf < 4; kf++) {
            uint32_t a[4][4], b[4][2];
#pragma unroll
            for (int fm = 0; fm < 4; fm++) {
                uint32_t ao = (uint32_t)(((warp_m * 64 + fm * 16 + (lane & 15)) * PSTR
                               + kf * 16 + (lane >> 4) * 8) * 2);
                ldsm_x4(a[fm], b0 + ao);
            }
#pragma unroll
            for (int fn = 0; fn < 4; fn++) {
                uint32_t bo = (uint32_t)(((warp_n * 32 + fn * 8 + (lane & 7)) * PSTR
                               + kf * 16 + ((lane >> 3) & 1) * 8) * 2);
                ldsm_x2(b[fn], b0 + PT16 * 2 + bo);
            }
#pragma unroll
            for (int fm = 0; fm < 4; fm++)
#pragma unroll
                for (int fn = 0; fn < 4; fn++)
                    mma_fp16(acc[fm][fn], a[fm], b[fn]);
        }
        __syncthreads();
    }

    int group = lane >> 2, tig = lane & 3;
#pragma unroll
    for (int fn = 0; fn < 4; fn++) {
        int n = (int)nb + warp_n * 32 + fn * 8 + 2 * tig;
        if (n < Nreal) {
            float bx = bi[n] + bh[n];
            float by = bi[n + 1] + bh[n + 1];
#pragma unroll
            for (int fm = 0; fm < 4; fm++) {
                size_t m = mb + warp_m * 64 + fm * 16 + group;
                float2 v0 = {acc[fm][fn][0] + bx, acc[fm][fn][1] + by};
                *(float2*)&Y[m * (size_t)Nreal + n] = v0;
                float2 v1 = {acc[fm][fn][2] + bx, acc[fm][fn][3] + by};
                *(float2*)&Y[(m + 8) * (size_t)Nreal + n] = v1;
            }
        }
    }
}

// ================= zero h buffers + barrier counter =================
__global__ void zero_hb_kernel() {
    int i = blockIdx.x * blockDim.x + threadIdx.x;
    if (i < 2 * 64 * 1152 / 2) ((uint32_t*)g_hfp)[i] = 0u;
    if (i == 0) g_count = 0;
}

// ================= fast activations (MUFU-based, err ~2^-20) =================
__device__ __forceinline__ float fsigmoid_(float x) {
    return __fdividef(1.f, 1.f + __expf(-x));
}
__device__ __forceinline__ float ftanh_(float x) {
    x = fminf(fmaxf(x, -15.f), 15.f);      // avoid inf/inf
    float e = __expf(2.f * x);
    return __fdividef(e - 1.f, e + 1.f);
}

// ================= fp16 HMMA persistent LSTM scan, warp-decoupled v2 =========
// R15 winner. R16 change: drop the redundant __threadfence before the arrive —
// red.release.gpu + the preceding __syncthreads already order all block h-writes.
template<int H, int KP, bool WX>
__global__ void __launch_bounds__(128, 1) scan_fp16_kernel(
    const float* __restrict__ xg,
    const __half* __restrict__ whh,
    float* __restrict__ out, int nb)
{
    constexpr int WSTR = KP + 8;
    constexpr int ASTR = 136;
    constexpr int NCH  = KP / 128;
    constexpr int G    = 4 * H;
    constexpr int SEGS = KP / 8;

    extern __shared__ __align__(16) char smx[];
    __half* Wh = (__half*)smx;
    __half* Ah = Wh + 32 * WSTR;          // per-warp: [4 bufs][16 rows][ASTR]

    int tid = threadIdx.x;
    int w = tid >> 5, lane = tid & 31;
    int g8 = lane >> 2, tig = lane & 3;
    int u0 = blockIdx.x * 8;
    bool uvalid = (u0 + 2 * tig) < H;

    for (int idx = tid; idx < 32 * SEGS; idx += 128) {
        int n = idx / SEGS, seg = idx - n * SEGS;
        int q = n >> 3, ui = n & 7, unit = u0 + ui;
        uint4 vh = {0,0,0,0};
        if (unit < H)
            vh = *(const uint4*)(whh + (size_t)(q * H + unit) * KP + seg * 8);
        *(uint4*)&Wh[n * WSTR + seg * 8] = vh;
    }
    __syncthreads();

    uint32_t wh_base = smem_u32(Wh);
    uint32_t ah_base = smem_u32(Ah) + (uint32_t)(w * 4 * 16 * ASTR * 2);

    // coalesced warp-private staging: per instr i, row = i*2 + (lane>>4),
    // seg = lane&15 -> lanes 0-15 cover a full 256 B row contiguously.
    int s_seg  = lane & 15;
    int s_half = lane >> 4;

    float cst[4] = {0.f, 0.f, 0.f, 0.f};

    int* cntp = &g_count;
    int m_row = w * 16 + g8;

    float2 xv[8];
    auto load_xv = [&](int t) {
#pragma unroll
        for (int mi = 0; mi < 2; mi++)
#pragma unroll
            for (int q = 0; q < 4; q++) {
                xv[mi * 4 + q] = make_float2(0.f, 0.f);
                if (uvalid) {
                    int m = m_row + mi * 8;
                    xv[mi * 4 + q] = *(const float2*)(xg + ((size_t)t * 64 + m) * G
                                                      + q * H + u0 + 2 * tig);
                }
            }
    };
    load_xv(0);

    for (int t = 0; t < T_STEPS; t++) {
        if (t > 0) {
            if (tid == 0) {
                int target = nb * t, v;
                do {
                    asm volatile("ld.acquire.gpu.global.s32 %0, [%1];"
                                 : "=r"(v) : "l"(cntp));
                } while (v < target);
            }
            __syncthreads();
        }

        const __half* hh = g_hfp[t & 1] + (size_t)(w * 16) * 1152;

        auto stage_chunk = [&](int c) {
            int b = c & 3, cc = c * 128;
#pragma unroll
            for (int i = 0; i < 8; i++) {
                int row = i * 2 + s_half;
                cp_async16(ah_base + (uint32_t)(((b * 16 + row) * ASTR + s_seg * 8) * 2),
                           hh + (size_t)row * 1152 + cc + s_seg * 8);
            }
        };

        float acc[4][4];
#pragma unroll
        for (int q = 0; q < 4; q++)
#pragma unroll
            for (int j = 0; j < 4; j++) acc[q][j] = 0.f;

        stage_chunk(0); CP_COMMIT();
        stage_chunk(1); CP_COMMIT();
        stage_chunk(2); CP_COMMIT();

        for (int c = 0; c < NCH; c++) {
            if (c + 3 < NCH) { stage_chunk(c + 3); CP_COMMIT(); CP_WAIT3(); }
            else {
                int r = NCH - 1 - c;
                if (r >= 3)      CP_WAIT3();
                else if (r == 2) CP_WAIT2();
                else if (r == 1) CP_WAIT1();
                else             CP_WAIT0();
            }
            __syncwarp();
            int b = c & 3;
#pragma unroll
            for (int j = 0; j < 8; j++) {
                uint32_t a[4];
                uint32_t a_off = ah_base + (uint32_t)(((b * 16 + (lane & 15)) * ASTR
                                  + j * 16 + (lane >> 4) * 8) * 2);
                ldsm_x4(a, a_off);
#pragma unroll
                for (int nf = 0; nf < 4; nf++) {
                    uint32_t bh[2];
                    uint32_t b_off = (uint32_t)(((nf * 8 + (lane & 7)) * WSTR
                                      + c * 128 + j * 16 + ((lane >> 3) & 1) * 8) * 2);
                    ldsm_x2(bh, wh_base + b_off);
                    mma_fp16(acc[nf], a, bh);
                }
            }
        }

        // ---- cell update: compute h, write ONLY hw, then arrive ----
        __half* hw = g_hfp[(t + 1) & 1];
        float hv[2][2];
#pragma unroll
        for (int mi = 0; mi < 2; mi++) {
#pragma unroll
            for (int uu = 0; uu < 2; uu++) {
                float xi = uu ? xv[mi * 4 + 0].y : xv[mi * 4 + 0].x;
                float xf = uu ? xv[mi * 4 + 1].y : xv[mi * 4 + 1].x;
                float xgg = uu ? xv[mi * 4 + 2].y : xv[mi * 4 + 2].x;
                float xo = uu ? xv[mi * 4 + 3].y : xv[mi * 4 + 3].x;
                float iraw = acc[0][mi * 2 + uu] + xi;
                float fraw = acc[1][mi * 2 + uu] + xf;
                float graw = acc[2][mi * 2 + uu] + xgg;
                float oraw = acc[3][mi * 2 + uu] + xo;
                float cn = fsigmoid_(fraw) * cst[mi * 2 + uu]
                         + fsigmoid_(iraw) * ftanh_(graw);
                cst[mi * 2 + uu] = cn;
                hv[mi][uu] = fsigmoid_(oraw) * ftanh_(cn);
            }
            if (uvalid) {
                int m = m_row + mi * 8;
                __half2 hp = __floats2half2_rn(hv[mi][0], hv[mi][1]);
                *(uint32_t*)&hw[(size_t)m * 1152 + u0 + 2 * tig] = *(uint32_t*)&hp;
            }
        }
        __syncthreads();                    // all h-writes done block-wide
        if (tid == 0)                       // release covers them (no membar needed)
            asm volatile("red.release.gpu.global.add.s32 [%0], %1;"
                         :: "l"(cntp), "r"(1) : "memory");

        // ---- hidden in the wait window: out stores, X stores, next xv ----
#pragma unroll
        for (int mi = 0; mi < 2; mi++) {
            int m = m_row + mi * 8;
            if (uvalid)
                *(float2*)&out[((size_t)t * 64 + m) * H + u0 + 2 * tig]
                    = make_float2(hv[mi][0], hv[mi][1]);
            if (WX) {
                uint32_t packed = 0u;
                if (uvalid) {
                    __half2 hp = __floats2half2_rn(hv[mi][0], hv[mi][1]);
                    packed = *(uint32_t*)&hp;
                }
                *(uint32_t*)&g_xf[((size_t)t * 64 + m) * 1152 + u0 + 2 * tig] = packed;
            }
        }
        if (t + 1 < T_STEPS) load_xv(t + 1);
    }
}

// ================= launch =================
extern "C" void kernel_launch(void* const* d_in, const int* in_sizes, int n_in,
                              void* d_out, int out_size)
{
    (void)in_sizes; (void)n_in; (void)out_size;
    const int*   tok = (const int*)d_in[0];
    const float* ew  = (const float*)d_in[1];
    const float* wih[3] = {(const float*)d_in[2], (const float*)d_in[6],  (const float*)d_in[10]};
    const float* whh[3] = {(const float*)d_in[3], (const float*)d_in[7],  (const float*)d_in[11]};
    const float* bih[3] = {(const float*)d_in[4], (const float*)d_in[8],  (const float*)d_in[12]};
    const float* bhh[3] = {(const float*)d_in[5], (const float*)d_in[9],  (const float*)d_in[13]};

    float* out  = (float*)d_out;
    float* out0 = out;
    float* out1 = out0 + (size_t)TB * NHID;
    float* out2 = out1 + (size_t)TB * NHID;

    void* p;
    cudaGetSymbolAddress(&p, g_xg);  float* xgf = (float*)p;
    cudaGetSymbolAddress(&p, g_xf);  __half* xf = (__half*)p;
    cudaGetSymbolAddress(&p, g_wf);  __half* wf = (__half*)p;

    const int PSM = 2 * 2 * PT16 * 2;                                    // 73,728 B
    const int SSM_BIG = (32 * (1152 + 8) + 4 * 64 * 136) * 2;            // 143,872 B
    const int SSM_SM  = (32 * (512 + 8)  + 4 * 64 * 136) * 2;            // 102,912 B
    cudaFuncSetAttribute(proj_f16_kernel<448>,
                         cudaFuncAttributeMaxDynamicSharedMemorySize, PSM);
    cudaFuncSetAttribute(proj_f16_kernel<1152>,
                         cudaFuncAttributeMaxDynamicSharedMemorySize, PSM);
    cudaFuncSetAttribute(scan_fp16_kernel<1150, 1152, true>,
                         cudaFuncAttributeMaxDynamicSharedMemorySize, SSM_BIG);
    cudaFuncSetAttribute(scan_fp16_kernel<400, 512, false>,
                         cudaFuncAttributeMaxDynamicSharedMemorySize, SSM_SM);

    auto cdiv = [](size_t a, int b) { return (int)((a + b - 1) / b); };
    const int ZHB = ((2 * 64 * 1152 / 2) + 255) / 256;

    embed_f16_kernel<<<cdiv((size_t)TB * 112, 256), 256>>>(tok, ew);

    // ---- layer 0: 400 -> 1150 ----
    conv_w_f16_kernel<<<cdiv(4608ull * 448, 256), 256>>>(wih[0], 4 * NHID, EMB, 448, 4608, wf);
    proj_f16_kernel<448><<<dim3(36, 256), 256, PSM>>>(xf, wf, bih[0], bhh[0], xgf, 4 * NHID);
    conv_w_f16_kernel<<<cdiv(4608ull * 1152, 256), 256>>>(whh[0], 4 * NHID, NHID, 1152, 4608, wf);
    zero_hb_kernel<<<ZHB, 256>>>();
    scan_fp16_kernel<1150, 1152, true><<<144, 128, SSM_BIG>>>(xgf, wf, out0, 144);

    // ---- layer 1: 1150 -> 1150 ----  (X written by scan0)
    conv_w_f16_kernel<<<cdiv(4608ull * 1152, 256), 256>>>(wih[1], 4 * NHID, NHID, 1152, 4608, wf);
    proj_f16_kernel<1152><<<dim3(36, 256), 256, PSM>>>(xf, wf, bih[1], bhh[1], xgf, 4 * NHID);
    conv_w_f16_kernel<<<cdiv(4608ull * 1152, 256), 256>>>(whh[1], 4 * NHID, NHID, 1152, 4608, wf);
    zero_hb_kernel<<<ZHB, 256>>>();
    scan_fp16_kernel<1150, 1152, true><<<144, 128, SSM_BIG>>>(xgf, wf, out1, 144);

    // ---- layer 2: 1150 -> 400 ----  (X written by scan1)
    conv_w_f16_kernel<<<cdiv(1664ull * 1152, 256), 256>>>(wih[2], 4 * 400, NHID, 1152, 1664, wf);
    proj_f16_kernel<1152><<<dim3(13, 256), 256, PSM>>>(xf, wf, bih[2], bhh[2], xgf, 4 * 400);
    conv_w_f16_kernel<<<cdiv(1600ull * 512, 256), 256>>>(whh[2], 4 * 400, 400, 512, 1600, wf);
    zero_hb_kernel<<<ZHB, 256>>>();
    scan_fp16_kernel<400, 512, false><<<50, 128, SSM_SM>>>(xgf, wf, out2, 50);
}